// round 1
// baseline (speedup 1.0000x reference)
#include <cuda_runtime.h>
#include <math.h>

#define HID 256
#define CND 128
#define KCL 16
#define PH  8
#define NMAX 262144
#define BMAX 2048

// ---------------- scratch (static device allocations; no cudaMalloc) -----
__device__ float d_hg[(size_t)NMAX * HID];       // gated atoms
__device__ float d_t [(size_t)NMAX * HID];       // gelu(hg@A1+ab1)
__device__ float d_S [(size_t)NMAX * KCL];       // soft assignments
__device__ float d_cluster[(size_t)BMAX * KCL * HID];
__device__ int   d_seg[BMAX + 1];
__device__ float d_u  [HID * PH];                // Wk_head @ q
__device__ float d_Qm [HID * PH];                // Wc @ u
__device__ float d_bq [PH];
__device__ float d_Wcv[HID * HID];               // Wc @ Wv
__device__ float d_bv [HID];                     // bc @ Wv

__device__ __forceinline__ float geluf(float x) {
    return 0.5f * x * (1.0f + erff(x * 0.7071067811865475f));
}

// ---------------- K0: segment starts from sorted batch -------------------
__global__ void k_seg(const int* __restrict__ batch, int N, int B) {
    int n = blockIdx.x * blockDim.x + threadIdx.x;
    if (n >= N) return;
    int bn = batch[n];
    if (n == 0) {
        for (int b = 0; b <= bn; b++) d_seg[b] = 0;
    } else {
        int bp = batch[n - 1];
        if (bn != bp) for (int b = bp + 1; b <= bn; b++) d_seg[b] = n;
    }
    if (n == N - 1) {
        for (int b = bn + 1; b <= B; b++) d_seg[b] = N;
    }
}

// ---------------- K4u: u[t][p] = sum_d Wk[t][p*32+d] * q[p][d] -----------
__global__ void k_u(const float* __restrict__ Wk, const float* __restrict__ q) {
    __shared__ float qs[HID];
    int tid = threadIdx.x;
    qs[tid] = q[tid];                       // q is PH*DH = 256 floats
    __syncthreads();
    int lane = tid & 31, p = tid >> 5;      // warp p handles head p
    for (int t = 0; t < HID; t++) {
        float v = Wk[(size_t)t * HID + tid] * qs[tid];
        #pragma unroll
        for (int off = 16; off; off >>= 1)
            v += __shfl_xor_sync(0xffffffffu, v, off);
        if (lane == 0) d_u[t * PH + p] = v;
    }
}

// ---------------- K4a: Wcv = Wc@Wv, bv = bc@Wv ---------------------------
__global__ __launch_bounds__(256) void k_wcv(
    const float* __restrict__ Wc, const float* __restrict__ Wv,
    const float* __restrict__ bc) {
    int i = blockIdx.x, j = threadIdx.x;
    float a = 0.f;
    if (i < HID) {
        #pragma unroll 4
        for (int t = 0; t < HID; t++)
            a += Wc[(size_t)i * HID + t] * Wv[(size_t)t * HID + j];
        d_Wcv[(size_t)i * HID + j] = a;
    } else {
        #pragma unroll 4
        for (int t = 0; t < HID; t++)
            a += bc[t] * Wv[(size_t)t * HID + j];
        d_bv[j] = a;
    }
}

// ---------------- K4b: Qm = Wc@u, bq = bc@u ------------------------------
__global__ __launch_bounds__(256) void k_qm(
    const float* __restrict__ Wc, const float* __restrict__ bc) {
    __shared__ float wrow[HID];
    __shared__ float ush[HID * PH];
    __shared__ float red[HID];
    int i = blockIdx.x, tid = threadIdx.x;
    wrow[tid] = (i < HID) ? Wc[(size_t)i * HID + tid] : bc[tid];
    for (int idx = tid; idx < HID * PH; idx += 256) ush[idx] = d_u[idx];
    __syncthreads();
    for (int p = 0; p < PH; p++) {
        red[tid] = wrow[tid] * ush[tid * PH + p];
        __syncthreads();
        for (int s = 128; s; s >>= 1) {
            if (tid < s) red[tid] += red[tid + s];
            __syncthreads();
        }
        if (tid == 0) { if (i < HID) d_Qm[i * PH + p] = red[0]; else d_bq[p] = red[0]; }
        __syncthreads();
    }
}

// ---------------- K1: fused gate GEMM + sigmoid gate ---------------------
// g = gelu([h|c] @ W1 + b1) ; alpha = sigmoid(g@W2+b2) ; hg = alpha*h
__global__ __launch_bounds__(256) void k_stage1(
    const float* __restrict__ h, const float* __restrict__ c,
    const float* __restrict__ W1, const float* __restrict__ b1,
    const float* __restrict__ W2, const float* __restrict__ b2, int N) {
    __shared__ __align__(16) float xs[32][32];
    __shared__ __align__(16) float ws[32][HID];
    __shared__ float w2s[HID];
    __shared__ float alps[32];
    int j  = threadIdx.x;
    int m0 = blockIdx.x * 32;
    float acc[32];
    #pragma unroll
    for (int m = 0; m < 32; m++) acc[m] = 0.f;

    for (int kt = 0; kt < HID + CND; kt += 32) {
        for (int i = j; i < 32 * 32; i += 256) {
            int m = i >> 5, kk = i & 31, col = kt + kk, row = m0 + m;
            float v = 0.f;
            if (row < N)
                v = (col < HID) ? h[(size_t)row * HID + col]
                                : c[(size_t)row * CND + (col - HID)];
            xs[m][kk] = v;
        }
        for (int i = j; i < 32 * HID; i += 256) {
            int kk = i >> 8, jj = i & 255;
            ws[kk][jj] = W1[(size_t)(kt + kk) * HID + jj];
        }
        __syncthreads();
        #pragma unroll
        for (int kk = 0; kk < 32; kk += 4) {
            float w0 = ws[kk][j], w1 = ws[kk + 1][j];
            float w2 = ws[kk + 2][j], w3 = ws[kk + 3][j];
            #pragma unroll
            for (int m = 0; m < 32; m++) {
                float4 xv = *(const float4*)&xs[m][kk];
                acc[m] += xv.x * w0 + xv.y * w1 + xv.z * w2 + xv.w * w3;
            }
        }
        __syncthreads();
    }
    // epilogue: gelu -> shared, per-row gate dot with W2
    float bj = b1[j];
    float (*gs)[HID] = (float(*)[HID])ws;
    #pragma unroll
    for (int m = 0; m < 32; m++) gs[m][j] = geluf(acc[m] + bj);
    w2s[j] = W2[j];
    __syncthreads();
    int warp = j >> 5, lane = j & 31;
    float b2v = b2[0];
    for (int r = 0; r < 4; r++) {
        int m = warp * 4 + r;
        float p = 0.f;
        #pragma unroll
        for (int i = 0; i < 8; i++) { int jj = lane + 32 * i; p += gs[m][jj] * w2s[jj]; }
        #pragma unroll
        for (int off = 16; off; off >>= 1) p += __shfl_xor_sync(0xffffffffu, p, off);
        if (lane == 0) alps[m] = 1.f / (1.f + expf(-(p + b2v)));
    }
    __syncthreads();
    #pragma unroll
    for (int m = 0; m < 32; m++) {
        int row = m0 + m;
        if (row < N)
            d_hg[(size_t)row * HID + j] = alps[m] * h[(size_t)row * HID + j];
    }
}

// ---------------- K2: t = gelu(hg @ A1 + ab1) ----------------------------
__global__ __launch_bounds__(256) void k_stage2(
    const float* __restrict__ A1, const float* __restrict__ ab1, int N) {
    __shared__ __align__(16) float xs[32][32];
    __shared__ __align__(16) float ws[32][HID];
    int j  = threadIdx.x;
    int m0 = blockIdx.x * 32;
    float acc[32];
    #pragma unroll
    for (int m = 0; m < 32; m++) acc[m] = 0.f;

    for (int kt = 0; kt < HID; kt += 32) {
        for (int i = j; i < 32 * 32; i += 256) {
            int m = i >> 5, kk = i & 31, row = m0 + m;
            xs[m][kk] = (row < N) ? d_hg[(size_t)row * HID + kt + kk] : 0.f;
        }
        for (int i = j; i < 32 * HID; i += 256) {
            int kk = i >> 8, jj = i & 255;
            ws[kk][jj] = A1[(size_t)(kt + kk) * HID + jj];
        }
        __syncthreads();
        #pragma unroll
        for (int kk = 0; kk < 32; kk += 4) {
            float w0 = ws[kk][j], w1 = ws[kk + 1][j];
            float w2 = ws[kk + 2][j], w3 = ws[kk + 3][j];
            #pragma unroll
            for (int m = 0; m < 32; m++) {
                float4 xv = *(const float4*)&xs[m][kk];
                acc[m] += xv.x * w0 + xv.y * w1 + xv.z * w2 + xv.w * w3;
            }
        }
        __syncthreads();
    }
    float bj = ab1[j];
    #pragma unroll
    for (int m = 0; m < 32; m++) {
        int row = m0 + m;
        if (row < N) d_t[(size_t)row * HID + j] = geluf(acc[m] + bj);
    }
}

// ---------------- K2b: S = softmax(t @ A2 + ab2) -------------------------
__global__ __launch_bounds__(256) void k_assign(
    const float* __restrict__ A2, const float* __restrict__ ab2, int N) {
    __shared__ float a2s[HID * KCL];
    int tid = threadIdx.x;
    for (int i = tid; i < HID * KCL; i += 256) a2s[i] = A2[i];
    __syncthreads();
    int warp = tid >> 5, lane = tid & 31;
    int n = blockIdx.x * 8 + warp;
    if (n >= N) return;
    if (lane < 16) {
        const float4* tp = (const float4*)(d_t + (size_t)n * HID);
        float lg = 0.f;
        #pragma unroll 4
        for (int j4 = 0; j4 < 64; j4++) {
            float4 tv = tp[j4];
            int jb = j4 * 4;
            lg += tv.x * a2s[(jb + 0) * KCL + lane];
            lg += tv.y * a2s[(jb + 1) * KCL + lane];
            lg += tv.z * a2s[(jb + 2) * KCL + lane];
            lg += tv.w * a2s[(jb + 3) * KCL + lane];
        }
        lg += ab2[lane];
        float mx = lg;
        #pragma unroll
        for (int off = 8; off; off >>= 1)
            mx = fmaxf(mx, __shfl_xor_sync(0xffffu, mx, off, 16));
        float e = expf(lg - mx), s = e;
        #pragma unroll
        for (int off = 8; off; off >>= 1)
            s += __shfl_xor_sync(0xffffu, s, off, 16);
        d_S[(size_t)n * KCL + lane] = e / s;
    }
}

// ---------------- K3: cluster[b,k,:] = sum_seg S[n,k]*hg[n,:] ------------
__global__ __launch_bounds__(256) void k_pool(void) {
    int b = blockIdx.x, tid = threadIdx.x;
    int s = d_seg[b], e = d_seg[b + 1];
    float acc[16];
    #pragma unroll
    for (int k = 0; k < 16; k++) acc[k] = 0.f;
    __shared__ __align__(16) float ssh[16 * 16];
    for (int n0 = s; n0 < e; n0 += 16) {
        int cnt = min(16, e - n0);
        if (tid < cnt * 16) ssh[tid] = d_S[(size_t)n0 * KCL + tid];
        __syncthreads();
        for (int a = 0; a < cnt; a++) {
            float hgv = d_hg[(size_t)(n0 + a) * HID + tid];
            const float4* sp = (const float4*)&ssh[a * 16];
            float4 s0 = sp[0], s1 = sp[1], s2 = sp[2], s3 = sp[3];
            acc[0]  += s0.x * hgv; acc[1]  += s0.y * hgv;
            acc[2]  += s0.z * hgv; acc[3]  += s0.w * hgv;
            acc[4]  += s1.x * hgv; acc[5]  += s1.y * hgv;
            acc[6]  += s1.z * hgv; acc[7]  += s1.w * hgv;
            acc[8]  += s2.x * hgv; acc[9]  += s2.y * hgv;
            acc[10] += s2.z * hgv; acc[11] += s2.w * hgv;
            acc[12] += s3.x * hgv; acc[13] += s3.y * hgv;
            acc[14] += s3.z * hgv; acc[15] += s3.w * hgv;
        }
        __syncthreads();
    }
    #pragma unroll
    for (int k = 0; k < 16; k++)
        d_cluster[((size_t)b * 16 + k) * HID + tid] = acc[k];
}

// ---------------- K5: attention readout + folded proj + LayerNorm --------
__global__ __launch_bounds__(256) void k_readout(
    const float* __restrict__ gamma, const float* __restrict__ beta,
    float* __restrict__ out) {
    int b = blockIdx.x, tid = threadIdx.x, lane = tid & 31, p = tid >> 5;
    __shared__ float cl[16][HID];
    __shared__ float qm[HID][9];        // pad 9 to kill stride-8 conflicts
    __shared__ float msh[PH][HID];
    __shared__ float wsh[PH][16];
    __shared__ float red[HID];
    __shared__ float bqs[PH];
    #pragma unroll
    for (int k = 0; k < 16; k++)
        cl[k][tid] = d_cluster[((size_t)b * 16 + k) * HID + tid];
    for (int idx = tid; idx < HID * PH; idx += 256)
        qm[idx >> 3][idx & 7] = d_Qm[idx];
    if (tid < PH) bqs[tid] = d_bq[tid];
    __syncthreads();

    // logits[p][k] : warp p, sequential k, lane-parallel dot of length 256
    float ml = 0.f;
    for (int k = 0; k < 16; k++) {
        float part = 0.f;
        #pragma unroll
        for (int i = 0; i < 8; i++) { int jj = lane + 32 * i; part += cl[k][jj] * qm[jj][p]; }
        #pragma unroll
        for (int off = 16; off; off >>= 1)
            part += __shfl_xor_sync(0xffffffffu, part, off);
        if (lane == k) ml = part;
    }
    const float scale = 0.17677669529663687f;   // 1/sqrt(32)
    if (lane < 16) {
        float lg = (ml + bqs[p]) * scale;
        float mx = lg;
        #pragma unroll
        for (int off = 8; off; off >>= 1)
            mx = fmaxf(mx, __shfl_xor_sync(0xffffu, mx, off, 16));
        float e = expf(lg - mx), su = e;
        #pragma unroll
        for (int off = 8; off; off >>= 1)
            su += __shfl_xor_sync(0xffffu, su, off, 16);
        wsh[p][lane] = e / su;
    }
    __syncthreads();

    // pooled raw cluster per head: m[p][j] = sum_k w[p][k]*cl[k][j]
    #pragma unroll
    for (int pp = 0; pp < PH; pp++) {
        float a = 0.f;
        #pragma unroll
        for (int k = 0; k < 16; k++) a += wsh[pp][k] * cl[k][tid];
        msh[pp][tid] = a;
    }
    __syncthreads();

    // out_pre[j] = m[p(j)] . Wcv[:,j] + bv[j]
    float o = d_bv[tid];
    #pragma unroll 8
    for (int i = 0; i < HID; i++)
        o += msh[p][i] * d_Wcv[(size_t)i * HID + tid];

    // LayerNorm
    red[tid] = o; __syncthreads();
    for (int s = 128; s; s >>= 1) { if (tid < s) red[tid] += red[tid + s]; __syncthreads(); }
    float mu = red[0] * (1.f / HID);
    __syncthreads();
    float dv = o - mu;
    red[tid] = dv * dv; __syncthreads();
    for (int s = 128; s; s >>= 1) { if (tid < s) red[tid] += red[tid + s]; __syncthreads(); }
    float var = red[0] * (1.f / HID);
    out[(size_t)b * HID + tid] = dv * rsqrtf(var + 1e-5f) * gamma[tid] + beta[tid];
}

// ---------------- launch --------------------------------------------------
extern "C" void kernel_launch(void* const* d_in, const int* in_sizes, int n_in,
                              void* d_out, int out_size) {
    const float* h_atom = (const float*)d_in[0];
    const float* c_atom = (const float*)d_in[1];
    const int*   batch  = (const int*)  d_in[2];
    const float* W1 = (const float*)d_in[3];
    const float* b1 = (const float*)d_in[4];
    const float* W2 = (const float*)d_in[5];
    const float* b2 = (const float*)d_in[6];
    const float* A1 = (const float*)d_in[7];
    const float* ab1 = (const float*)d_in[8];
    const float* A2 = (const float*)d_in[9];
    const float* ab2 = (const float*)d_in[10];
    const float* Wc = (const float*)d_in[11];
    const float* bc = (const float*)d_in[12];
    const float* q  = (const float*)d_in[13];
    const float* Wk = (const float*)d_in[14];
    const float* Wv = (const float*)d_in[15];
    const float* gamma = (const float*)d_in[16];
    const float* beta  = (const float*)d_in[17];
    float* out = (float*)d_out;

    int N = in_sizes[0] / HID; if (N > NMAX) N = NMAX;
    int B = out_size / HID;    if (B > BMAX) B = BMAX;

    k_seg<<<(N + 255) / 256, 256>>>(batch, N, B);
    k_u<<<1, 256>>>(Wk, q);
    k_wcv<<<HID + 1, 256>>>(Wc, Wv, bc);
    k_qm<<<HID + 1, 256>>>(Wc, bc);
    k_stage1<<<(N + 31) / 32, 256>>>(h_atom, c_atom, W1, b1, W2, b2, N);
    k_stage2<<<(N + 31) / 32, 256>>>(A1, ab1, N);
    k_assign<<<(N + 7) / 8, 256>>>(A2, ab2, N);
    k_pool<<<B, 256>>>();
    k_readout<<<B, 256>>>(gamma, beta, out);
}

// round 2
// speedup vs baseline: 2.0300x; 2.0300x over previous
#include <cuda_runtime.h>
#include <math.h>

#define HID 256
#define CND 128
#define KCL 16
#define PH  8
#define NMAX 262144
#define BMAX 2048
#define BM 64
#define BK 32
#define BMP 68   // padded xs row stride (keeps 16B alignment, reduces STS conflicts)

// ---------------- scratch (static device allocations; no cudaMalloc) -----
__device__ float d_hg[(size_t)NMAX * HID];       // gated atoms
__device__ float d_t [(size_t)NMAX * HID];       // gelu(hg@A1+ab1)
__device__ float d_S [(size_t)NMAX * KCL];       // soft assignments
__device__ float d_cluster[(size_t)BMAX * KCL * HID];
__device__ int   d_seg[BMAX + 1];
__device__ float d_u  [HID * PH];                // Wk_head @ q
__device__ float d_Qm [HID * PH];                // Wc @ u
__device__ float d_bq [PH];
__device__ float d_Wcv[HID * HID];               // Wc @ Wv
__device__ float d_bv [HID];                     // bc @ Wv

__device__ __forceinline__ float geluf(float x) {
    return 0.5f * x * (1.0f + erff(x * 0.7071067811865475f));
}

// packed 2xf32 FMA (FFMA2) and duplicate-pack
#define FFMA2(d, a, b) \
    asm("fma.rn.f32x2 %0, %1, %2, %0;" : "+l"(d) : "l"(a), "l"(b))
#define PACKDUP(d, f) \
    asm("mov.b64 %0, {%1, %1};" : "=l"(d) : "r"(__float_as_uint(f)))

// ---------------- K0: segment starts from sorted batch -------------------
__global__ void k_seg(const int* __restrict__ batch, int N, int B) {
    int n = blockIdx.x * blockDim.x + threadIdx.x;
    if (n >= N) return;
    int bn = batch[n];
    if (n == 0) {
        for (int b = 0; b <= bn; b++) d_seg[b] = 0;
    } else {
        int bp = batch[n - 1];
        if (bn != bp) for (int b = bp + 1; b <= bn; b++) d_seg[b] = n;
    }
    if (n == N - 1) {
        for (int b = bn + 1; b <= B; b++) d_seg[b] = N;
    }
}

// ---------------- K4u: u[t][p] = sum_d Wk[t][p*32+d] * q[p][d] -----------
__global__ void k_u(const float* __restrict__ Wk, const float* __restrict__ q) {
    __shared__ float qs[HID];
    int tid = threadIdx.x;
    qs[tid] = q[tid];                       // q is PH*DH = 256 floats
    __syncthreads();
    int lane = tid & 31, p = tid >> 5;      // warp p handles head p
    for (int t = 0; t < HID; t++) {
        float v = Wk[(size_t)t * HID + tid] * qs[tid];
        #pragma unroll
        for (int off = 16; off; off >>= 1)
            v += __shfl_xor_sync(0xffffffffu, v, off);
        if (lane == 0) d_u[t * PH + p] = v;
    }
}

// ---------------- K4a: Wcv = Wc@Wv, bv = bc@Wv ---------------------------
__global__ __launch_bounds__(256) void k_wcv(
    const float* __restrict__ Wc, const float* __restrict__ Wv,
    const float* __restrict__ bc) {
    int i = blockIdx.x, j = threadIdx.x;
    float a = 0.f;
    if (i < HID) {
        #pragma unroll 4
        for (int t = 0; t < HID; t++)
            a += Wc[(size_t)i * HID + t] * Wv[(size_t)t * HID + j];
        d_Wcv[(size_t)i * HID + j] = a;
    } else {
        #pragma unroll 4
        for (int t = 0; t < HID; t++)
            a += bc[t] * Wv[(size_t)t * HID + j];
        d_bv[j] = a;
    }
}

// ---------------- K4b: Qm = Wc@u, bq = bc@u (warp-shuffle version) -------
__global__ __launch_bounds__(256) void k_qm(
    const float* __restrict__ Wc, const float* __restrict__ bc) {
    __shared__ float wrow[HID];
    int i = blockIdx.x, tid = threadIdx.x;
    wrow[tid] = (i < HID) ? Wc[(size_t)i * HID + tid] : bc[tid];
    __syncthreads();
    int p = tid >> 5, lane = tid & 31;      // warp p handles head p
    float v = 0.f;
    #pragma unroll
    for (int t = 0; t < 8; t++) {
        int idx = lane + 32 * t;
        v += wrow[idx] * d_u[idx * PH + p];
    }
    #pragma unroll
    for (int off = 16; off; off >>= 1)
        v += __shfl_xor_sync(0xffffffffu, v, off);
    if (lane == 0) { if (i < HID) d_Qm[i * PH + p] = v; else d_bq[p] = v; }
}

// ---------------- K1: fused gate GEMM (FFMA2) + sigmoid gate -------------
// g = gelu([h|c] @ W1 + b1) ; alpha = sigmoid(g@W2+b2) ; hg = alpha*h
__global__ __launch_bounds__(256, 2) void k_stage1(
    const float* __restrict__ h, const float* __restrict__ c,
    const float* __restrict__ W1, const float* __restrict__ b1,
    const float* __restrict__ W2, const float* __restrict__ b2, int N) {
    __shared__ __align__(16) float xs[BK][BMP];   // K-transposed input tile
    __shared__ __align__(16) float ws[BK][HID];   // weight tile
    __shared__ float red[4][2][16];
    __shared__ float alps[BM];

    int tid = threadIdx.x;
    int tx = tid & 63, ty = tid >> 6;
    int m0 = ty * 16;            // 16 rows per thread
    int j0 = tx * 4;             // 4 cols per thread
    int r0 = blockIdx.x * BM;

    int lrow = tid >> 3;         // loader: row 0..31 (two rounds)
    int lk4  = (tid & 7) * 4;    // loader: k offset

    unsigned long long acc[8][4];
    #pragma unroll
    for (int i = 0; i < 8; i++)
        #pragma unroll
        for (int cc = 0; cc < 4; cc++) acc[i][cc] = 0ull;

    for (int kt = 0; kt < HID + CND; kt += BK) {
        const float* src; int stride, cb;
        if (kt < HID) { src = h; stride = HID; cb = kt; }
        else          { src = c; stride = CND; cb = kt - HID; }
        int ra = r0 + lrow, rb = r0 + lrow + 32;
        float4 xv0 = make_float4(0.f, 0.f, 0.f, 0.f);
        float4 xv1 = make_float4(0.f, 0.f, 0.f, 0.f);
        if (ra < N) xv0 = *(const float4*)(src + (size_t)ra * stride + cb + lk4);
        if (rb < N) xv1 = *(const float4*)(src + (size_t)rb * stride + cb + lk4);
        float4 wv[8];
        #pragma unroll
        for (int i = 0; i < 8; i++) {
            int li = tid + i * 256;            // float4 index in [0,2048)
            int kk = li >> 6, jj = (li & 63) * 4;
            wv[i] = *(const float4*)(W1 + (size_t)(kt + kk) * HID + jj);
        }
        __syncthreads();
        xs[lk4 + 0][lrow] = xv0.x; xs[lk4 + 1][lrow] = xv0.y;
        xs[lk4 + 2][lrow] = xv0.z; xs[lk4 + 3][lrow] = xv0.w;
        xs[lk4 + 0][lrow + 32] = xv1.x; xs[lk4 + 1][lrow + 32] = xv1.y;
        xs[lk4 + 2][lrow + 32] = xv1.z; xs[lk4 + 3][lrow + 32] = xv1.w;
        #pragma unroll
        for (int i = 0; i < 8; i++) {
            int li = tid + i * 256;
            int kk = li >> 6, jj = (li & 63) * 4;
            *(float4*)&ws[kk][jj] = wv[i];
        }
        __syncthreads();
        #pragma unroll 8
        for (int k = 0; k < BK; k++) {
            ulonglong2 xA = *(const ulonglong2*)&xs[k][m0];
            ulonglong2 xB = *(const ulonglong2*)&xs[k][m0 + 4];
            ulonglong2 xC = *(const ulonglong2*)&xs[k][m0 + 8];
            ulonglong2 xD = *(const ulonglong2*)&xs[k][m0 + 12];
            float4 w4 = *(const float4*)&ws[k][j0];
            unsigned long long wd0, wd1, wd2, wd3;
            PACKDUP(wd0, w4.x); PACKDUP(wd1, w4.y);
            PACKDUP(wd2, w4.z); PACKDUP(wd3, w4.w);
            FFMA2(acc[0][0], xA.x, wd0); FFMA2(acc[0][1], xA.x, wd1);
            FFMA2(acc[0][2], xA.x, wd2); FFMA2(acc[0][3], xA.x, wd3);
            FFMA2(acc[1][0], xA.y, wd0); FFMA2(acc[1][1], xA.y, wd1);
            FFMA2(acc[1][2], xA.y, wd2); FFMA2(acc[1][3], xA.y, wd3);
            FFMA2(acc[2][0], xB.x, wd0); FFMA2(acc[2][1], xB.x, wd1);
            FFMA2(acc[2][2], xB.x, wd2); FFMA2(acc[2][3], xB.x, wd3);
            FFMA2(acc[3][0], xB.y, wd0); FFMA2(acc[3][1], xB.y, wd1);
            FFMA2(acc[3][2], xB.y, wd2); FFMA2(acc[3][3], xB.y, wd3);
            FFMA2(acc[4][0], xC.x, wd0); FFMA2(acc[4][1], xC.x, wd1);
            FFMA2(acc[4][2], xC.x, wd2); FFMA2(acc[4][3], xC.x, wd3);
            FFMA2(acc[5][0], xC.y, wd0); FFMA2(acc[5][1], xC.y, wd1);
            FFMA2(acc[5][2], xC.y, wd2); FFMA2(acc[5][3], xC.y, wd3);
            FFMA2(acc[6][0], xD.x, wd0); FFMA2(acc[6][1], xD.x, wd1);
            FFMA2(acc[6][2], xD.x, wd2); FFMA2(acc[6][3], xD.x, wd3);
            FFMA2(acc[7][0], xD.y, wd0); FFMA2(acc[7][1], xD.y, wd1);
            FFMA2(acc[7][2], xD.y, wd2); FFMA2(acc[7][3], xD.y, wd3);
        }
    }
    // epilogue: gelu + per-row dot with W2 (cross-thread via shfl + shared)
    float4 bj4 = *(const float4*)(b1 + j0);
    float bj[4] = {bj4.x, bj4.y, bj4.z, bj4.w};
    float4 w24 = *(const float4*)(W2 + j0);
    float w2r[4] = {w24.x, w24.y, w24.z, w24.w};
    float part[16];
    #pragma unroll
    for (int i = 0; i < 8; i++) {
        float plo = 0.f, phi = 0.f;
        #pragma unroll
        for (int cc = 0; cc < 4; cc++) {
            unsigned long long u = acc[i][cc];
            float glo = geluf(__uint_as_float((unsigned)u) + bj[cc]);
            float ghi = geluf(__uint_as_float((unsigned)(u >> 32)) + bj[cc]);
            plo += glo * w2r[cc];
            phi += ghi * w2r[cc];
        }
        part[2 * i] = plo; part[2 * i + 1] = phi;
    }
    #pragma unroll
    for (int r = 0; r < 16; r++) {
        float v = part[r];
        #pragma unroll
        for (int off = 16; off; off >>= 1)
            v += __shfl_xor_sync(0xffffffffu, v, off);
        part[r] = v;
    }
    int lane = tid & 31, half = (tid >> 5) & 1;
    if (lane == 0) {
        #pragma unroll
        for (int r = 0; r < 16; r++) red[ty][half][r] = part[r];
    }
    __syncthreads();
    if (tid < BM) {
        float s = red[tid >> 4][0][tid & 15] + red[tid >> 4][1][tid & 15] + b2[0];
        alps[tid] = 1.f / (1.f + expf(-s));
    }
    __syncthreads();
    #pragma unroll
    for (int r = 0; r < 16; r++) {
        int row = r0 + m0 + r;
        if (row < N) {
            float4 hv = *(const float4*)(h + (size_t)row * HID + j0);
            float a = alps[m0 + r];
            float4 o = make_float4(a * hv.x, a * hv.y, a * hv.z, a * hv.w);
            *(float4*)(d_hg + (size_t)row * HID + j0) = o;
        }
    }
}

// ---------------- K2: t = gelu(hg @ A1 + ab1)  (FFMA2) -------------------
__global__ __launch_bounds__(256, 2) void k_stage2(
    const float* __restrict__ A1, const float* __restrict__ ab1, int N) {
    __shared__ __align__(16) float xs[BK][BMP];
    __shared__ __align__(16) float ws[BK][HID];

    int tid = threadIdx.x;
    int tx = tid & 63, ty = tid >> 6;
    int m0 = ty * 16;
    int j0 = tx * 4;
    int r0 = blockIdx.x * BM;

    int lrow = tid >> 3;
    int lk4  = (tid & 7) * 4;

    unsigned long long acc[8][4];
    #pragma unroll
    for (int i = 0; i < 8; i++)
        #pragma unroll
        for (int cc = 0; cc < 4; cc++) acc[i][cc] = 0ull;

    for (int kt = 0; kt < HID; kt += BK) {
        int ra = r0 + lrow, rb = r0 + lrow + 32;
        float4 xv0 = make_float4(0.f, 0.f, 0.f, 0.f);
        float4 xv1 = make_float4(0.f, 0.f, 0.f, 0.f);
        if (ra < N) xv0 = *(const float4*)(d_hg + (size_t)ra * HID + kt + lk4);
        if (rb < N) xv1 = *(const float4*)(d_hg + (size_t)rb * HID + kt + lk4);
        float4 wv[8];
        #pragma unroll
        for (int i = 0; i < 8; i++) {
            int li = tid + i * 256;
            int kk = li >> 6, jj = (li & 63) * 4;
            wv[i] = *(const float4*)(A1 + (size_t)(kt + kk) * HID + jj);
        }
        __syncthreads();
        xs[lk4 + 0][lrow] = xv0.x; xs[lk4 + 1][lrow] = xv0.y;
        xs[lk4 + 2][lrow] = xv0.z; xs[lk4 + 3][lrow] = xv0.w;
        xs[lk4 + 0][lrow + 32] = xv1.x; xs[lk4 + 1][lrow + 32] = xv1.y;
        xs[lk4 + 2][lrow + 32] = xv1.z; xs[lk4 + 3][lrow + 32] = xv1.w;
        #pragma unroll
        for (int i = 0; i < 8; i++) {
            int li = tid + i * 256;
            int kk = li >> 6, jj = (li & 63) * 4;
            *(float4*)&ws[kk][jj] = wv[i];
        }
        __syncthreads();
        #pragma unroll 8
        for (int k = 0; k < BK; k++) {
            ulonglong2 xA = *(const ulonglong2*)&xs[k][m0];
            ulonglong2 xB = *(const ulonglong2*)&xs[k][m0 + 4];
            ulonglong2 xC = *(const ulonglong2*)&xs[k][m0 + 8];
            ulonglong2 xD = *(const ulonglong2*)&xs[k][m0 + 12];
            float4 w4 = *(const float4*)&ws[k][j0];
            unsigned long long wd0, wd1, wd2, wd3;
            PACKDUP(wd0, w4.x); PACKDUP(wd1, w4.y);
            PACKDUP(wd2, w4.z); PACKDUP(wd3, w4.w);
            FFMA2(acc[0][0], xA.x, wd0); FFMA2(acc[0][1], xA.x, wd1);
            FFMA2(acc[0][2], xA.x, wd2); FFMA2(acc[0][3], xA.x, wd3);
            FFMA2(acc[1][0], xA.y, wd0); FFMA2(acc[1][1], xA.y, wd1);
            FFMA2(acc[1][2], xA.y, wd2); FFMA2(acc[1][3], xA.y, wd3);
            FFMA2(acc[2][0], xB.x, wd0); FFMA2(acc[2][1], xB.x, wd1);
            FFMA2(acc[2][2], xB.x, wd2); FFMA2(acc[2][3], xB.x, wd3);
            FFMA2(acc[3][0], xB.y, wd0); FFMA2(acc[3][1], xB.y, wd1);
            FFMA2(acc[3][2], xB.y, wd2); FFMA2(acc[3][3], xB.y, wd3);
            FFMA2(acc[4][0], xC.x, wd0); FFMA2(acc[4][1], xC.x, wd1);
            FFMA2(acc[4][2], xC.x, wd2); FFMA2(acc[4][3], xC.x, wd3);
            FFMA2(acc[5][0], xC.y, wd0); FFMA2(acc[5][1], xC.y, wd1);
            FFMA2(acc[5][2], xC.y, wd2); FFMA2(acc[5][3], xC.y, wd3);
            FFMA2(acc[6][0], xD.x, wd0); FFMA2(acc[6][1], xD.x, wd1);
            FFMA2(acc[6][2], xD.x, wd2); FFMA2(acc[6][3], xD.x, wd3);
            FFMA2(acc[7][0], xD.y, wd0); FFMA2(acc[7][1], xD.y, wd1);
            FFMA2(acc[7][2], xD.y, wd2); FFMA2(acc[7][3], xD.y, wd3);
        }
    }
    float4 bj4 = *(const float4*)(ab1 + j0);
    float bj[4] = {bj4.x, bj4.y, bj4.z, bj4.w};
    #pragma unroll
    for (int i = 0; i < 8; i++) {
        int rlo = r0 + m0 + 2 * i;
        float4 olo, ohi;
        unsigned long long u0 = acc[i][0], u1 = acc[i][1];
        unsigned long long u2 = acc[i][2], u3 = acc[i][3];
        olo.x = geluf(__uint_as_float((unsigned)u0) + bj[0]);
        olo.y = geluf(__uint_as_float((unsigned)u1) + bj[1]);
        olo.z = geluf(__uint_as_float((unsigned)u2) + bj[2]);
        olo.w = geluf(__uint_as_float((unsigned)u3) + bj[3]);
        ohi.x = geluf(__uint_as_float((unsigned)(u0 >> 32)) + bj[0]);
        ohi.y = geluf(__uint_as_float((unsigned)(u1 >> 32)) + bj[1]);
        ohi.z = geluf(__uint_as_float((unsigned)(u2 >> 32)) + bj[2]);
        ohi.w = geluf(__uint_as_float((unsigned)(u3 >> 32)) + bj[3]);
        if (rlo < N)     *(float4*)(d_t + (size_t)rlo * HID + j0) = olo;
        if (rlo + 1 < N) *(float4*)(d_t + (size_t)(rlo + 1) * HID + j0) = ohi;
    }
}

// ---------------- K2b: S = softmax(t @ A2 + ab2) -------------------------
__global__ __launch_bounds__(256) void k_assign(
    const float* __restrict__ A2, const float* __restrict__ ab2, int N) {
    __shared__ float a2s[HID * KCL];
    int tid = threadIdx.x;
    for (int i = tid; i < HID * KCL; i += 256) a2s[i] = A2[i];
    __syncthreads();
    int warp = tid >> 5, lane = tid & 31;
    int n = blockIdx.x * 8 + warp;
    if (n >= N) return;
    if (lane < 16) {
        const float4* tp = (const float4*)(d_t + (size_t)n * HID);
        float lg = 0.f;
        #pragma unroll 4
        for (int j4 = 0; j4 < 64; j4++) {
            float4 tv = tp[j4];
            int jb = j4 * 4;
            lg += tv.x * a2s[(jb + 0) * KCL + lane];
            lg += tv.y * a2s[(jb + 1) * KCL + lane];
            lg += tv.z * a2s[(jb + 2) * KCL + lane];
            lg += tv.w * a2s[(jb + 3) * KCL + lane];
        }
        lg += ab2[lane];
        float mx = lg;
        #pragma unroll
        for (int off = 8; off; off >>= 1)
            mx = fmaxf(mx, __shfl_xor_sync(0xffffu, mx, off, 16));
        float e = expf(lg - mx), s = e;
        #pragma unroll
        for (int off = 8; off; off >>= 1)
            s += __shfl_xor_sync(0xffffu, s, off, 16);
        d_S[(size_t)n * KCL + lane] = e / s;
    }
}

// ---------------- K3: cluster[b,k,:] = sum_seg S[n,k]*hg[n,:] ------------
__global__ __launch_bounds__(256) void k_pool(void) {
    int b = blockIdx.x, tid = threadIdx.x;
    int s = d_seg[b], e = d_seg[b + 1];
    float acc[16];
    #pragma unroll
    for (int k = 0; k < 16; k++) acc[k] = 0.f;
    __shared__ __align__(16) float ssh[16 * 16];
    for (int n0 = s; n0 < e; n0 += 16) {
        int cnt = min(16, e - n0);
        if (tid < cnt * 16) ssh[tid] = d_S[(size_t)n0 * KCL + tid];
        __syncthreads();
        for (int a = 0; a < cnt; a++) {
            float hgv = d_hg[(size_t)(n0 + a) * HID + tid];
            const float4* sp = (const float4*)&ssh[a * 16];
            float4 s0 = sp[0], s1 = sp[1], s2 = sp[2], s3 = sp[3];
            acc[0]  += s0.x * hgv; acc[1]  += s0.y * hgv;
            acc[2]  += s0.z * hgv; acc[3]  += s0.w * hgv;
            acc[4]  += s1.x * hgv; acc[5]  += s1.y * hgv;
            acc[6]  += s1.z * hgv; acc[7]  += s1.w * hgv;
            acc[8]  += s2.x * hgv; acc[9]  += s2.y * hgv;
            acc[10] += s2.z * hgv; acc[11] += s2.w * hgv;
            acc[12] += s3.x * hgv; acc[13] += s3.y * hgv;
            acc[14] += s3.z * hgv; acc[15] += s3.w * hgv;
        }
        __syncthreads();
    }
    #pragma unroll
    for (int k = 0; k < 16; k++)
        d_cluster[((size_t)b * 16 + k) * HID + tid] = acc[k];
}

// ---------------- K5: attention readout + folded proj + LayerNorm --------
__global__ __launch_bounds__(256) void k_readout(
    const float* __restrict__ gamma, const float* __restrict__ beta,
    float* __restrict__ out) {
    int b = blockIdx.x, tid = threadIdx.x, lane = tid & 31, p = tid >> 5;
    __shared__ float cl[16][HID];
    __shared__ float qm[HID][9];        // pad 9 to kill stride-8 conflicts
    __shared__ float msh[PH][HID];
    __shared__ float wsh[PH][16];
    __shared__ float red[HID];
    __shared__ float bqs[PH];
    #pragma unroll
    for (int k = 0; k < 16; k++)
        cl[k][tid] = d_cluster[((size_t)b * 16 + k) * HID + tid];
    for (int idx = tid; idx < HID * PH; idx += 256)
        qm[idx >> 3][idx & 7] = d_Qm[idx];
    if (tid < PH) bqs[tid] = d_bq[tid];
    __syncthreads();

    float ml = 0.f;
    for (int k = 0; k < 16; k++) {
        float part = 0.f;
        #pragma unroll
        for (int i = 0; i < 8; i++) { int jj = lane + 32 * i; part += cl[k][jj] * qm[jj][p]; }
        #pragma unroll
        for (int off = 16; off; off >>= 1)
            part += __shfl_xor_sync(0xffffffffu, part, off);
        if (lane == k) ml = part;
    }
    const float scale = 0.17677669529663687f;   // 1/sqrt(32)
    if (lane < 16) {
        float lg = (ml + bqs[p]) * scale;
        float mx = lg;
        #pragma unroll
        for (int off = 8; off; off >>= 1)
            mx = fmaxf(mx, __shfl_xor_sync(0xffffu, mx, off, 16));
        float e = expf(lg - mx), su = e;
        #pragma unroll
        for (int off = 8; off; off >>= 1)
            su += __shfl_xor_sync(0xffffu, su, off, 16);
        wsh[p][lane] = e / su;
    }
    __syncthreads();

    #pragma unroll
    for (int pp = 0; pp < PH; pp++) {
        float a = 0.f;
        #pragma unroll
        for (int k = 0; k < 16; k++) a += wsh[pp][k] * cl[k][tid];
        msh[pp][tid] = a;
    }
    __syncthreads();

    float o = d_bv[tid];
    #pragma unroll 8
    for (int i = 0; i < HID; i++)
        o += msh[p][i] * d_Wcv[(size_t)i * HID + tid];

    red[tid] = o; __syncthreads();
    for (int s = 128; s; s >>= 1) { if (tid < s) red[tid] += red[tid + s]; __syncthreads(); }
    float mu = red[0] * (1.f / HID);
    __syncthreads();
    float dv = o - mu;
    red[tid] = dv * dv; __syncthreads();
    for (int s = 128; s; s >>= 1) { if (tid < s) red[tid] += red[tid + s]; __syncthreads(); }
    float var = red[0] * (1.f / HID);
    out[(size_t)b * HID + tid] = dv * rsqrtf(var + 1e-5f) * gamma[tid] + beta[tid];
}

// ---------------- launch --------------------------------------------------
extern "C" void kernel_launch(void* const* d_in, const int* in_sizes, int n_in,
                              void* d_out, int out_size) {
    const float* h_atom = (const float*)d_in[0];
    const float* c_atom = (const float*)d_in[1];
    const int*   batch  = (const int*)  d_in[2];
    const float* W1 = (const float*)d_in[3];
    const float* b1 = (const float*)d_in[4];
    const float* W2 = (const float*)d_in[5];
    const float* b2 = (const float*)d_in[6];
    const float* A1 = (const float*)d_in[7];
    const float* ab1 = (const float*)d_in[8];
    const float* A2 = (const float*)d_in[9];
    const float* ab2 = (const float*)d_in[10];
    const float* Wc = (const float*)d_in[11];
    const float* bc = (const float*)d_in[12];
    const float* q  = (const float*)d_in[13];
    const float* Wk = (const float*)d_in[14];
    const float* Wv = (const float*)d_in[15];
    const float* gamma = (const float*)d_in[16];
    const float* beta  = (const float*)d_in[17];
    float* out = (float*)d_out;

    int N = in_sizes[0] / HID; if (N > NMAX) N = NMAX;
    int B = out_size / HID;    if (B > BMAX) B = BMAX;

    k_seg<<<(N + 255) / 256, 256>>>(batch, N, B);
    k_u<<<1, 256>>>(Wk, q);
    k_wcv<<<HID + 1, 256>>>(Wc, Wv, bc);
    k_qm<<<HID + 1, 256>>>(Wc, bc);
    k_stage1<<<(N + BM - 1) / BM, 256>>>(h_atom, c_atom, W1, b1, W2, b2, N);
    k_stage2<<<(N + BM - 1) / BM, 256>>>(A1, ab1, N);
    k_assign<<<(N + 7) / 8, 256>>>(A2, ab2, N);
    k_pool<<<B, 256>>>();
    k_readout<<<B, 256>>>(gamma, beta, out);
}

// round 4
// speedup vs baseline: 3.0608x; 1.5078x over previous
#include <cuda_runtime.h>
#include <cuda_bf16.h>
#include <math.h>
#include <stdint.h>

#define HID 256
#define CND 128
#define KCL 16
#define PH  8
#define NMAX 262144
#define BMAX 2048

// ---------------- scratch (static device allocations) --------------------
__device__ float d_hg[(size_t)NMAX * HID];
__device__ float d_S [(size_t)NMAX * KCL];
__device__ float d_cluster[(size_t)BMAX * KCL * HID];
__device__ int   d_seg[BMAX + 1];
__device__ float d_u  [HID * PH];
__device__ float d_Qm [HID * PH];
__device__ float d_bq [PH];
__device__ float d_Wcv[HID * HID];
__device__ float d_bv [HID];
__device__ float d_gpart[2 * NMAX];            // gate partials per col-half
__device__ float d_lgpart[2 * (size_t)NMAX * KCL];  // logit partials
// split-transposed weights (K-major [N rows][K cols])
__device__ __nv_bfloat16 d_w1t_hi[256 * 384];
__device__ __nv_bfloat16 d_w1t_lo[256 * 384];
__device__ __nv_bfloat16 d_a1t_hi[256 * 256];
__device__ __nv_bfloat16 d_a1t_lo[256 * 256];

__device__ __forceinline__ float geluf(float x) {
    return 0.5f * x * (1.0f + erff(x * 0.7071067811865475f));
}
__device__ __forceinline__ uint32_t smem_u32(const void* p) {
    uint32_t a;
    asm("{ .reg .u64 t; cvta.to.shared.u64 t, %1; cvt.u32.u64 %0, t; }"
        : "=r"(a) : "l"(p));
    return a;
}

#define SW128(o) ((o) ^ (((o) >> 3) & 0x70))

#define LDSM_X4(r, addr) \
    asm volatile("ldmatrix.sync.aligned.m8n8.x4.shared.b16 {%0,%1,%2,%3}, [%4];" \
        : "=r"((r)[0]), "=r"((r)[1]), "=r"((r)[2]), "=r"((r)[3]) : "r"(addr))
#define LDSM_X2(r, addr) \
    asm volatile("ldmatrix.sync.aligned.m8n8.x2.shared.b16 {%0,%1}, [%2];" \
        : "=r"((r)[0]), "=r"((r)[1]) : "r"(addr))
#define MMA16816(c, a, b) \
    asm volatile("mma.sync.aligned.m16n8k16.row.col.f32.bf16.bf16.f32 " \
        "{%0,%1,%2,%3}, {%4,%5,%6,%7}, {%8,%9}, {%0,%1,%2,%3};" \
        : "+f"((c)[0]), "+f"((c)[1]), "+f"((c)[2]), "+f"((c)[3]) \
        : "r"((a)[0]), "r"((a)[1]), "r"((a)[2]), "r"((a)[3]), \
          "r"((b)[0]), "r"((b)[1]))

// smem layout (bytes)
#define S_AHI  0
#define S_ALO  16384
#define S_BHI  32768
#define S_BLO  49152
#define S_BIAS 65536   // 128 f32
#define S_AUX  66048   // w2s (128 f32) or A2s (128x16 f32)
#define S_RED  74240   // gate_s (128) or lg_s (128x16)
#define SMEMSZ 82432

// ---------------- tiny prep kernels --------------------------------------
__global__ void k_splitw1(const float* __restrict__ W) {
    int t = blockIdx.x, j = threadIdx.x;            // W[384][256] -> WT[256][384]
    float v = W[(size_t)t * 256 + j];
    __nv_bfloat16 h = __float2bfloat16(v);
    __nv_bfloat16 l = __float2bfloat16(v - __bfloat162float(h));
    d_w1t_hi[(size_t)j * 384 + t] = h;
    d_w1t_lo[(size_t)j * 384 + t] = l;
}
__global__ void k_splita1(const float* __restrict__ A) {
    int t = blockIdx.x, j = threadIdx.x;
    float v = A[(size_t)t * 256 + j];
    __nv_bfloat16 h = __float2bfloat16(v);
    __nv_bfloat16 l = __float2bfloat16(v - __bfloat162float(h));
    d_a1t_hi[(size_t)j * 256 + t] = h;
    d_a1t_lo[(size_t)j * 256 + t] = l;
}

// ---------------- K0: segment starts -------------------------------------
__global__ void k_seg(const int* __restrict__ batch, int N, int B) {
    int n = blockIdx.x * blockDim.x + threadIdx.x;
    if (n >= N) return;
    int bn = batch[n];
    if (n == 0) {
        for (int b = 0; b <= bn; b++) d_seg[b] = 0;
    } else {
        int bp = batch[n - 1];
        if (bn != bp) for (int b = bp + 1; b <= bn; b++) d_seg[b] = n;
    }
    if (n == N - 1) {
        for (int b = bn + 1; b <= B; b++) d_seg[b] = N;
    }
}

// ---------------- readout prep -------------------------------------------
__global__ void k_u(const float* __restrict__ Wk, const float* __restrict__ q) {
    __shared__ float qs[HID];
    int tid = threadIdx.x;
    qs[tid] = q[tid];
    __syncthreads();
    int lane = tid & 31, p = tid >> 5;
    for (int t = 0; t < HID; t++) {
        float v = Wk[(size_t)t * HID + tid] * qs[tid];
        #pragma unroll
        for (int off = 16; off; off >>= 1)
            v += __shfl_xor_sync(0xffffffffu, v, off);
        if (lane == 0) d_u[t * PH + p] = v;
    }
}
__global__ __launch_bounds__(256) void k_wcv(
    const float* __restrict__ Wc, const float* __restrict__ Wv,
    const float* __restrict__ bc) {
    int i = blockIdx.x, j = threadIdx.x;
    float a = 0.f;
    if (i < HID) {
        #pragma unroll 4
        for (int t = 0; t < HID; t++)
            a += Wc[(size_t)i * HID + t] * Wv[(size_t)t * HID + j];
        d_Wcv[(size_t)i * HID + j] = a;
    } else {
        #pragma unroll 4
        for (int t = 0; t < HID; t++)
            a += bc[t] * Wv[(size_t)t * HID + j];
        d_bv[j] = a;
    }
}
__global__ __launch_bounds__(256) void k_qm(
    const float* __restrict__ Wc, const float* __restrict__ bc) {
    __shared__ float wrow[HID];
    int i = blockIdx.x, tid = threadIdx.x;
    wrow[tid] = (i < HID) ? Wc[(size_t)i * HID + tid] : bc[tid];
    __syncthreads();
    int p = tid >> 5, lane = tid & 31;
    float v = 0.f;
    #pragma unroll
    for (int t = 0; t < 8; t++) {
        int idx = lane + 32 * t;
        v += wrow[idx] * d_u[idx * PH + p];
    }
    #pragma unroll
    for (int off = 16; off; off >>= 1)
        v += __shfl_xor_sync(0xffffffffu, v, off);
    if (lane == 0) { if (i < HID) d_Qm[i * PH + p] = v; else d_bq[p] = v; }
}

// ======================= mma.sync GEMM kernel =============================
// grid: (ceil(N/128), 2). blockIdx.y = which 128-col half of the 256 outputs.
// STAGE1: D = [h|c]@W1 -> gelu -> partial gate dot W2 -> d_gpart
// STAGE2: D = d_hg@A1  -> gelu -> partial @A2        -> d_lgpart
template <int STAGE1>
__global__ __launch_bounds__(256, 2)
void k_gemm(const float* __restrict__ X1, const float* __restrict__ X2,
            const float* __restrict__ bias, const float* __restrict__ W2,
            const float* __restrict__ A2, int N) {
    extern __shared__ __align__(1024) char smem[];
    uint32_t sb = smem_u32(smem);
    int tid = threadIdx.x, lane = tid & 31, wid = tid >> 5;
    int wm = wid & 1, wn = wid >> 1;
    int r0 = blockIdx.x * 128;
    int half = blockIdx.y;
    const int CHUNKS = STAGE1 ? 6 : 4;
    const int KW = STAGE1 ? 384 : 256;

    float* bias_s = (float*)(smem + S_BIAS);
    float* aux_s  = (float*)(smem + S_AUX);
    float* red_s  = (float*)(smem + S_RED);

    if (tid < 128) bias_s[tid] = bias[half * 128 + tid];
    if (STAGE1) {
        if (tid < 128) aux_s[tid] = W2[half * 128 + tid];
    } else {
        for (int i = tid; i < 128 * 16; i += 256)
            aux_s[i] = A2[(size_t)(half * 128 + (i >> 4)) * 16 + (i & 15)];
    }

    float acc[4][4][4];
    #pragma unroll
    for (int a = 0; a < 4; a++)
        #pragma unroll
        for (int b = 0; b < 4; b++)
            #pragma unroll
            for (int e = 0; e < 4; e++) acc[a][b][e] = 0.f;

    const __nv_bfloat16* Bhi = STAGE1 ? d_w1t_hi : d_a1t_hi;
    const __nv_bfloat16* Blo = STAGE1 ? d_w1t_lo : d_a1t_lo;

    for (int ch = 0; ch < CHUNKS; ch++) {
        int kt = ch * 64;
        __syncthreads();   // previous chunk's MMAs done reading smem
        // ---- A tile [128 x 64] f32 -> split bf16 hi/lo, SW128 -----------
        {
            const float* src; int stride, cb;
            if (STAGE1) {
                if (kt < 256) { src = X1; stride = 256; cb = kt; }
                else          { src = X2; stride = 128; cb = kt - 256; }
            } else { src = d_hg; stride = 256; cb = kt; }
            #pragma unroll
            for (int i = 0; i < 8; i++) {
                int idx = tid + i * 256;
                int row = idx >> 4, c4 = (idx & 15) * 4;
                int gr = r0 + row;
                float4 v = make_float4(0.f, 0.f, 0.f, 0.f);
                if (gr < N) v = *(const float4*)(src + (size_t)gr * stride + cb + c4);
                __nv_bfloat16 h0 = __float2bfloat16(v.x), h1 = __float2bfloat16(v.y);
                __nv_bfloat16 h2 = __float2bfloat16(v.z), h3 = __float2bfloat16(v.w);
                __nv_bfloat16 l0 = __float2bfloat16(v.x - __bfloat162float(h0));
                __nv_bfloat16 l1 = __float2bfloat16(v.y - __bfloat162float(h1));
                __nv_bfloat16 l2 = __float2bfloat16(v.z - __bfloat162float(h2));
                __nv_bfloat16 l3 = __float2bfloat16(v.w - __bfloat162float(h3));
                uint32_t off = SW128((uint32_t)(row * 128 + c4 * 2));
                uint2 ph_ = make_uint2(
                    (uint32_t)__bfloat16_as_ushort(h0) | ((uint32_t)__bfloat16_as_ushort(h1) << 16),
                    (uint32_t)__bfloat16_as_ushort(h2) | ((uint32_t)__bfloat16_as_ushort(h3) << 16));
                uint2 pl_ = make_uint2(
                    (uint32_t)__bfloat16_as_ushort(l0) | ((uint32_t)__bfloat16_as_ushort(l1) << 16),
                    (uint32_t)__bfloat16_as_ushort(l2) | ((uint32_t)__bfloat16_as_ushort(l3) << 16));
                *(uint2*)(smem + S_AHI + off) = ph_;
                *(uint2*)(smem + S_ALO + off) = pl_;
            }
        }
        // ---- B tiles [128 n x 64 k] bf16 hi/lo, SW128 -------------------
        #pragma unroll
        for (int i = 0; i < 4; i++) {
            int u = tid + i * 256;
            int row = u >> 3, c8 = (u & 7) * 8;
            int nG = half * 128 + row;
            uint4 vh = *(const uint4*)(Bhi + (size_t)nG * KW + kt + c8);
            uint4 vl = *(const uint4*)(Blo + (size_t)nG * KW + kt + c8);
            uint32_t off = SW128((uint32_t)(row * 128 + c8 * 2));
            *(uint4*)(smem + S_BHI + off) = vh;
            *(uint4*)(smem + S_BLO + off) = vl;
        }
        __syncthreads();
        // ---- compute: 4 k16 steps, 3 split passes -----------------------
        #pragma unroll
        for (int ks = 0; ks < 4; ks++) {
            int kb = ks * 32;
            uint32_t bh[4][2], bl[4][2];
            #pragma unroll
            for (int nt = 0; nt < 4; nt++) {
                int nb = wn * 32 + nt * 8 + (lane & 7);
                uint32_t ao = SW128((uint32_t)(nb * 128 + kb + ((lane & 8) ? 16 : 0)));
                LDSM_X2(bh[nt], sb + S_BHI + ao);
                LDSM_X2(bl[nt], sb + S_BLO + ao);
            }
            #pragma unroll
            for (int mt = 0; mt < 4; mt++) {
                int mb = wm * 64 + mt * 16 + (lane & 7) + ((lane & 8) ? 8 : 0);
                uint32_t ao = SW128((uint32_t)(mb * 128 + kb + ((lane & 16) ? 16 : 0)));
                uint32_t ah[4], al[4];
                LDSM_X4(ah, sb + S_AHI + ao);
                LDSM_X4(al, sb + S_ALO + ao);
                #pragma unroll
                for (int nt = 0; nt < 4; nt++) {
                    MMA16816(acc[mt][nt], ah, bh[nt]);
                    MMA16816(acc[mt][nt], al, bh[nt]);
                    MMA16816(acc[mt][nt], ah, bl[nt]);
                }
            }
        }
    }
    __syncthreads();

    // ======================= epilogue ====================================
    if (STAGE1) {
        if (tid < 128) red_s[tid] = 0.f;
        __syncthreads();
        #pragma unroll
        for (int mt = 0; mt < 4; mt++) {
            float s0 = 0.f, s1 = 0.f;
            #pragma unroll
            for (int nt = 0; nt < 4; nt++) {
                int n = wn * 32 + nt * 8 + (lane & 3) * 2;
                float b0v = bias_s[n], b1v = bias_s[n + 1];
                float w0 = aux_s[n],  w1v = aux_s[n + 1];
                s0 += geluf(acc[mt][nt][0] + b0v) * w0
                    + geluf(acc[mt][nt][1] + b1v) * w1v;
                s1 += geluf(acc[mt][nt][2] + b0v) * w0
                    + geluf(acc[mt][nt][3] + b1v) * w1v;
            }
            s0 += __shfl_xor_sync(0xffffffffu, s0, 1);
            s0 += __shfl_xor_sync(0xffffffffu, s0, 2);
            s1 += __shfl_xor_sync(0xffffffffu, s1, 1);
            s1 += __shfl_xor_sync(0xffffffffu, s1, 2);
            if ((lane & 3) == 0) {
                int rb = wm * 64 + mt * 16 + (lane >> 2);
                atomicAdd(&red_s[rb], s0);
                atomicAdd(&red_s[rb + 8], s1);
            }
        }
        __syncthreads();
        if (tid < 128 && r0 + tid < N)
            d_gpart[(size_t)half * NMAX + r0 + tid] = red_s[tid];
    } else {
        for (int i = tid; i < 128 * 16; i += 256) red_s[i] = 0.f;
        __syncthreads();
        #pragma unroll
        for (int mt = 0; mt < 4; mt++) {
            float l0[16], l1[16];
            #pragma unroll
            for (int k = 0; k < 16; k++) { l0[k] = 0.f; l1[k] = 0.f; }
            #pragma unroll
            for (int nt = 0; nt < 4; nt++) {
                int n = wn * 32 + nt * 8 + (lane & 3) * 2;
                #pragma unroll
                for (int e = 0; e < 4; e++) {
                    float v = geluf(acc[mt][nt][e] + bias_s[n + (e & 1)]);
                    const float* ar = &aux_s[(n + (e & 1)) * 16];
                    float* dst = (e < 2) ? l0 : l1;
                    #pragma unroll
                    for (int k = 0; k < 16; k++) dst[k] += v * ar[k];
                }
            }
            #pragma unroll
            for (int k = 0; k < 16; k++) {
                l0[k] += __shfl_xor_sync(0xffffffffu, l0[k], 1);
                l0[k] += __shfl_xor_sync(0xffffffffu, l0[k], 2);
                l1[k] += __shfl_xor_sync(0xffffffffu, l1[k], 1);
                l1[k] += __shfl_xor_sync(0xffffffffu, l1[k], 2);
            }
            if ((lane & 3) == 0) {
                int rb = wm * 64 + mt * 16 + (lane >> 2);
                #pragma unroll
                for (int k = 0; k < 16; k++) {
                    atomicAdd(&red_s[rb * 16 + k], l0[k]);
                    atomicAdd(&red_s[(rb + 8) * 16 + k], l1[k]);
                }
            }
        }
        __syncthreads();
        for (int i = tid; i < 128 * 16; i += 256) {
            int row = i >> 4, gr = r0 + row;
            if (gr < N)
                d_lgpart[(size_t)half * NMAX * 16 + (size_t)gr * 16 + (i & 15)] = red_s[i];
        }
    }
}

// ---------------- combine: alpha = sigmoid(sum), hg = alpha*h ------------
__global__ __launch_bounds__(256) void k_gate(
    const float* __restrict__ h, const float* __restrict__ b2, int N) {
    __shared__ float al[128];
    int tid = threadIdx.x;
    int r0 = blockIdx.x * 128;
    if (tid < 128) {
        int gr = r0 + tid;
        float s = 0.f;
        if (gr < N) s = d_gpart[gr] + d_gpart[NMAX + gr];
        al[tid] = 1.f / (1.f + expf(-(s + b2[0])));
    }
    __syncthreads();
    #pragma unroll
    for (int i = 0; i < 32; i++) {
        int idx = tid + i * 256;          // 128 rows * 64 float4
        int row = idx >> 6, c4 = (idx & 63) * 4;
        int gr = r0 + row;
        if (gr < N) {
            float4 hv = *(const float4*)(h + (size_t)gr * 256 + c4);
            float a = al[row];
            float4 o = make_float4(a * hv.x, a * hv.y, a * hv.z, a * hv.w);
            *(float4*)(d_hg + (size_t)gr * 256 + c4) = o;
        }
    }
}

// ---------------- combine: softmax of logit partials -> d_S --------------
__global__ __launch_bounds__(256) void k_soft(
    const float* __restrict__ ab2, int N) {
    __shared__ float ab2s[16];
    int tid = threadIdx.x;
    if (tid < 16) ab2s[tid] = ab2[tid];
    __syncthreads();
    int n = blockIdx.x * 256 + tid;
    if (n >= N) return;
    float l[16], mx = -1e30f;
    const float4* p0 = (const float4*)(d_lgpart + (size_t)n * 16);
    const float4* p1 = (const float4*)(d_lgpart + (size_t)NMAX * 16 + (size_t)n * 16);
    #pragma unroll
    for (int k4 = 0; k4 < 4; k4++) {
        float4 a = p0[k4], b = p1[k4];
        l[4*k4+0] = a.x + b.x + ab2s[4*k4+0];
        l[4*k4+1] = a.y + b.y + ab2s[4*k4+1];
        l[4*k4+2] = a.z + b.z + ab2s[4*k4+2];
        l[4*k4+3] = a.w + b.w + ab2s[4*k4+3];
    }
    #pragma unroll
    for (int k = 0; k < 16; k++) mx = fmaxf(mx, l[k]);
    float s = 0.f;
    #pragma unroll
    for (int k = 0; k < 16; k++) { l[k] = expf(l[k] - mx); s += l[k]; }
    float inv = 1.f / s;
    #pragma unroll
    for (int k4 = 0; k4 < 4; k4++) {
        float4 o = make_float4(l[4*k4] * inv, l[4*k4+1] * inv,
                               l[4*k4+2] * inv, l[4*k4+3] * inv);
        *(float4*)(d_S + (size_t)n * 16 + 4 * k4) = o;
    }
}

// ---------------- K3: segment pool ---------------------------------------
__global__ __launch_bounds__(256) void k_pool(void) {
    int b = blockIdx.x, tid = threadIdx.x;
    int s = d_seg[b], e = d_seg[b + 1];
    float acc[16];
    #pragma unroll
    for (int k = 0; k < 16; k++) acc[k] = 0.f;
    __shared__ __align__(16) float ssh[16 * 16];
    for (int n0 = s; n0 < e; n0 += 16) {
        int cnt = min(16, e - n0);
        if (tid < cnt * 16) ssh[tid] = d_S[(size_t)n0 * KCL + tid];
        __syncthreads();
        for (int a = 0; a < cnt; a++) {
            float hgv = d_hg[(size_t)(n0 + a) * HID + tid];
            const float4* sp = (const float4*)&ssh[a * 16];
            float4 s0 = sp[0], s1 = sp[1], s2 = sp[2], s3 = sp[3];
            acc[0]  += s0.x * hgv; acc[1]  += s0.y * hgv;
            acc[2]  += s0.z * hgv; acc[3]  += s0.w * hgv;
            acc[4]  += s1.x * hgv; acc[5]  += s1.y * hgv;
            acc[6]  += s1.z * hgv; acc[7]  += s1.w * hgv;
            acc[8]  += s2.x * hgv; acc[9]  += s2.y * hgv;
            acc[10] += s2.z * hgv; acc[11] += s2.w * hgv;
            acc[12] += s3.x * hgv; acc[13] += s3.y * hgv;
            acc[14] += s3.z * hgv; acc[15] += s3.w * hgv;
        }
        __syncthreads();
    }
    #pragma unroll
    for (int k = 0; k < 16; k++)
        d_cluster[((size_t)b * 16 + k) * HID + tid] = acc[k];
}

// ---------------- K5: attention readout + folded proj + LN ---------------
__global__ __launch_bounds__(256) void k_readout(
    const float* __restrict__ gamma, const float* __restrict__ beta,
    float* __restrict__ out) {
    int b = blockIdx.x, tid = threadIdx.x, lane = tid & 31, p = tid >> 5;
    __shared__ float cl[16][HID];
    __shared__ float qm[HID][9];
    __shared__ float msh[PH][HID];
    __shared__ float wsh[PH][16];
    __shared__ float red[HID];
    __shared__ float bqs[PH];
    #pragma unroll
    for (int k = 0; k < 16; k++)
        cl[k][tid] = d_cluster[((size_t)b * 16 + k) * HID + tid];
    for (int idx = tid; idx < HID * PH; idx += 256)
        qm[idx >> 3][idx & 7] = d_Qm[idx];
    if (tid < PH) bqs[tid] = d_bq[tid];
    __syncthreads();

    float ml = 0.f;
    for (int k = 0; k < 16; k++) {
        float part = 0.f;
        #pragma unroll
        for (int i = 0; i < 8; i++) { int jj = lane + 32 * i; part += cl[k][jj] * qm[jj][p]; }
        #pragma unroll
        for (int off = 16; off; off >>= 1)
            part += __shfl_xor_sync(0xffffffffu, part, off);
        if (lane == k) ml = part;
    }
    const float scale = 0.17677669529663687f;
    if (lane < 16) {
        float lgv = (ml + bqs[p]) * scale;
        float mx = lgv;
        #pragma unroll
        for (int off = 8; off; off >>= 1)
            mx = fmaxf(mx, __shfl_xor_sync(0xffffu, mx, off, 16));
        float e = expf(lgv - mx), su = e;
        #pragma unroll
        for (int off = 8; off; off >>= 1)
            su += __shfl_xor_sync(0xffffu, su, off, 16);
        wsh[p][lane] = e / su;
    }
    __syncthreads();

    #pragma unroll
    for (int pp = 0; pp < PH; pp++) {
        float a = 0.f;
        #pragma unroll
        for (int k = 0; k < 16; k++) a += wsh[pp][k] * cl[k][tid];
        msh[pp][tid] = a;
    }
    __syncthreads();

    float o = d_bv[tid];
    #pragma unroll 8
    for (int i = 0; i < HID; i++)
        o += msh[p][i] * d_Wcv[(size_t)i * HID + tid];

    red[tid] = o; __syncthreads();
    for (int s = 128; s; s >>= 1) { if (tid < s) red[tid] += red[tid + s]; __syncthreads(); }
    float mu = red[0] * (1.f / HID);
    __syncthreads();
    float dv = o - mu;
    red[tid] = dv * dv; __syncthreads();
    for (int s = 128; s; s >>= 1) { if (tid < s) red[tid] += red[tid + s]; __syncthreads(); }
    float var = red[0] * (1.f / HID);
    out[(size_t)b * HID + tid] = dv * rsqrtf(var + 1e-5f) * gamma[tid] + beta[tid];
}

// ---------------- launch --------------------------------------------------
extern "C" void kernel_launch(void* const* d_in, const int* in_sizes, int n_in,
                              void* d_out, int out_size) {
    const float* h_atom = (const float*)d_in[0];
    const float* c_atom = (const float*)d_in[1];
    const int*   batch  = (const int*)  d_in[2];
    const float* W1 = (const float*)d_in[3];
    const float* b1 = (const float*)d_in[4];
    const float* W2 = (const float*)d_in[5];
    const float* b2 = (const float*)d_in[6];
    const float* A1 = (const float*)d_in[7];
    const float* ab1 = (const float*)d_in[8];
    const float* A2 = (const float*)d_in[9];
    const float* ab2 = (const float*)d_in[10];
    const float* Wc = (const float*)d_in[11];
    const float* bc = (const float*)d_in[12];
    const float* q  = (const float*)d_in[13];
    const float* Wk = (const float*)d_in[14];
    const float* Wv = (const float*)d_in[15];
    const float* gamma = (const float*)d_in[16];
    const float* beta  = (const float*)d_in[17];
    float* out = (float*)d_out;

    int N = in_sizes[0] / HID; if (N > NMAX) N = NMAX;
    int B = out_size / HID;    if (B > BMAX) B = BMAX;

    cudaFuncSetAttribute(k_gemm<1>, cudaFuncAttributeMaxDynamicSharedMemorySize, SMEMSZ);
    cudaFuncSetAttribute(k_gemm<0>, cudaFuncAttributeMaxDynamicSharedMemorySize, SMEMSZ);

    k_seg<<<(N + 255) / 256, 256>>>(batch, N, B);
    k_splitw1<<<384, 256>>>(W1);
    k_splita1<<<256, 256>>>(A1);
    k_u<<<1, 256>>>(Wk, q);
    k_wcv<<<HID + 1, 256>>>(Wc, Wv, bc);
    k_qm<<<HID + 1, 256>>>(Wc, bc);

    int gtiles = (N + 127) / 128;
    k_gemm<1><<<dim3(gtiles, 2), 256, SMEMSZ>>>(h_atom, c_atom, b1, W2, nullptr, N);
    k_gate<<<gtiles, 256>>>(h_atom, b2, N);
    k_gemm<0><<<dim3(gtiles, 2), 256, SMEMSZ>>>(nullptr, nullptr, ab1, nullptr, A2, N);
    k_soft<<<(N + 255) / 256, 256>>>(ab2, N);
    k_pool<<<B, 256>>>();
    k_readout<<<B, 256>>>(gamma, beta, out);
}

// round 5
// speedup vs baseline: 3.5239x; 1.1513x over previous
#include <cuda_runtime.h>
#include <cuda_bf16.h>
#include <math.h>
#include <stdint.h>

#define HID 256
#define CND 128
#define KCL 16
#define PH  8
#define NMAX 262144
#define BMAX 2048

// ---------------- scratch (static device allocations) --------------------
__device__ float d_hg[(size_t)NMAX * HID];
__device__ float d_S [(size_t)NMAX * KCL];
__device__ float d_cluster[(size_t)BMAX * KCL * HID];
__device__ int   d_seg[BMAX + 1];
__device__ float d_u  [HID * PH];
__device__ float d_Qm [HID * PH];
__device__ float d_bq [PH];
__device__ float d_Wcv[HID * HID];
__device__ float d_bv [HID];
// split-transposed weights (K-major [N rows][K cols])
__device__ __nv_bfloat16 d_w1t_hi[256 * 384];
__device__ __nv_bfloat16 d_w1t_lo[256 * 384];
__device__ __nv_bfloat16 d_a1t_hi[256 * 256];
__device__ __nv_bfloat16 d_a1t_lo[256 * 256];

__device__ __forceinline__ float geluf(float x) {
    return 0.5f * x * (1.0f + erff(x * 0.7071067811865475f));
}
__device__ __forceinline__ uint32_t smem_u32(const void* p) {
    uint32_t a;
    asm("{ .reg .u64 t; cvta.to.shared.u64 t, %1; cvt.u32.u64 %0, t; }"
        : "=r"(a) : "l"(p));
    return a;
}

#define SW128(o) ((o) ^ (((o) >> 3) & 0x70))

#define LDSM_X4(r, addr) \
    asm volatile("ldmatrix.sync.aligned.m8n8.x4.shared.b16 {%0,%1,%2,%3}, [%4];" \
        : "=r"((r)[0]), "=r"((r)[1]), "=r"((r)[2]), "=r"((r)[3]) : "r"(addr))
#define LDSM_X2(r, addr) \
    asm volatile("ldmatrix.sync.aligned.m8n8.x2.shared.b16 {%0,%1}, [%2];" \
        : "=r"((r)[0]), "=r"((r)[1]) : "r"(addr))
#define MMA16816(c, a, b) \
    asm volatile("mma.sync.aligned.m16n8k16.row.col.f32.bf16.bf16.f32 " \
        "{%0,%1,%2,%3}, {%4,%5,%6,%7}, {%8,%9}, {%0,%1,%2,%3};" \
        : "+f"((c)[0]), "+f"((c)[1]), "+f"((c)[2]), "+f"((c)[3]) \
        : "r"((a)[0]), "r"((a)[1]), "r"((a)[2]), "r"((a)[3]), \
          "r"((b)[0]), "r"((b)[1]))

// smem byte layout for k_fused (all swizzle regions 1024-aligned)
#define S_BIAS1 0        // 256 f32
#define S_W2    1024     // 256 f32
#define S_AB1   2048     // 256 f32
#define S_AB2   3072     // 16 f32
#define S_ALPHA 3136     // 128 f32
#define S_A2S   4096     // 256*16 f32 = 16384
#define S_REDG  20480    // 128 f32
#define S_RED2  20992    // 128*16 f32 = 8192  (ends 29184)
#define R1      29696    // 32KB: stage1 A hi/lo, later hg chunk 3
#define R2      62464    // 64KB: B hi (32KB) + B lo (32KB)
#define R3      128000   // 96KB: hg chunks 0..2 (hi/lo 16KB each)
#define SMEMSZ  226304

// ---------------- tiny prep kernels --------------------------------------
__global__ void k_splitw1(const float* __restrict__ W) {
    int t = blockIdx.x, j = threadIdx.x;            // W[384][256] -> WT[256][384]
    float v = W[(size_t)t * 256 + j];
    __nv_bfloat16 h = __float2bfloat16(v);
    __nv_bfloat16 l = __float2bfloat16(v - __bfloat162float(h));
    d_w1t_hi[(size_t)j * 384 + t] = h;
    d_w1t_lo[(size_t)j * 384 + t] = l;
}
__global__ void k_splita1(const float* __restrict__ A) {
    int t = blockIdx.x, j = threadIdx.x;
    float v = A[(size_t)t * 256 + j];
    __nv_bfloat16 h = __float2bfloat16(v);
    __nv_bfloat16 l = __float2bfloat16(v - __bfloat162float(h));
    d_a1t_hi[(size_t)j * 256 + t] = h;
    d_a1t_lo[(size_t)j * 256 + t] = l;
}

// ---------------- K0: segment starts -------------------------------------
__global__ void k_seg(const int* __restrict__ batch, int N, int B) {
    int n = blockIdx.x * blockDim.x + threadIdx.x;
    if (n >= N) return;
    int bn = batch[n];
    if (n == 0) {
        for (int b = 0; b <= bn; b++) d_seg[b] = 0;
    } else {
        int bp = batch[n - 1];
        if (bn != bp) for (int b = bp + 1; b <= bn; b++) d_seg[b] = n;
    }
    if (n == N - 1) {
        for (int b = bn + 1; b <= B; b++) d_seg[b] = N;
    }
}

// ---------------- readout prep (parallel) --------------------------------
__global__ void k_u2(const float* __restrict__ Wk, const float* __restrict__ q) {
    __shared__ float qs[HID];
    int tid = threadIdx.x, t = blockIdx.x;
    qs[tid] = q[tid];
    __syncthreads();
    int lane = tid & 31, p = tid >> 5;
    float v = Wk[(size_t)t * HID + tid] * qs[tid];
    #pragma unroll
    for (int off = 16; off; off >>= 1)
        v += __shfl_xor_sync(0xffffffffu, v, off);
    if (lane == 0) d_u[t * PH + p] = v;
}
__global__ __launch_bounds__(256) void k_wcv(
    const float* __restrict__ Wc, const float* __restrict__ Wv,
    const float* __restrict__ bc) {
    int i = blockIdx.x, j = threadIdx.x;
    float a = 0.f;
    if (i < HID) {
        #pragma unroll 4
        for (int t = 0; t < HID; t++)
            a += Wc[(size_t)i * HID + t] * Wv[(size_t)t * HID + j];
        d_Wcv[(size_t)i * HID + j] = a;
    } else {
        #pragma unroll 4
        for (int t = 0; t < HID; t++)
            a += bc[t] * Wv[(size_t)t * HID + j];
        d_bv[j] = a;
    }
}
__global__ __launch_bounds__(256) void k_qm(
    const float* __restrict__ Wc, const float* __restrict__ bc) {
    __shared__ float wrow[HID];
    int i = blockIdx.x, tid = threadIdx.x;
    wrow[tid] = (i < HID) ? Wc[(size_t)i * HID + tid] : bc[tid];
    __syncthreads();
    int p = tid >> 5, lane = tid & 31;
    float v = 0.f;
    #pragma unroll
    for (int t = 0; t < 8; t++) {
        int idx = lane + 32 * t;
        v += wrow[idx] * d_u[idx * PH + p];
    }
    #pragma unroll
    for (int off = 16; off; off >>= 1)
        v += __shfl_xor_sync(0xffffffffu, v, off);
    if (lane == 0) { if (i < HID) d_Qm[i * PH + p] = v; else d_bq[p] = v; }
}

// ======================= fused atom kernel ================================
// Per 128-row tile: D1=[h|c]@W1 -> gate -> alpha -> hg (global f32 + smem split)
//                   D2=hg@A1 (A from smem) -> gelu -> @A2 -> softmax -> d_S
__global__ void __launch_bounds__(512, 1) k_fused(
    const float* __restrict__ h, const float* __restrict__ c,
    const float* __restrict__ b1, const float* __restrict__ W2,
    const float* __restrict__ b2, const float* __restrict__ ab1,
    const float* __restrict__ A2, const float* __restrict__ ab2, int N) {
    extern __shared__ __align__(1024) char smem[];
    uint32_t sb = smem_u32(smem);
    int tid = threadIdx.x, lane = tid & 31, wid = tid >> 5;
    int wm = wid & 3, wn = wid >> 2;     // 4 x 4 warp grid: 32 rows x 64 cols
    int r0 = blockIdx.x * 128;

    float* bias1 = (float*)(smem + S_BIAS1);
    float* w2s   = (float*)(smem + S_W2);
    float* ab1s  = (float*)(smem + S_AB1);
    float* ab2s  = (float*)(smem + S_AB2);
    float* alpha = (float*)(smem + S_ALPHA);
    float* a2s   = (float*)(smem + S_A2S);
    float* redg  = (float*)(smem + S_REDG);
    float* red2  = (float*)(smem + S_RED2);

    if (tid < 256) {
        bias1[tid] = b1[tid];
        w2s[tid]   = W2[tid];
        ab1s[tid]  = ab1[tid];
    }
    if (tid < 16) ab2s[tid] = ab2[tid];
    for (int i = tid; i < 256 * 16; i += 512) a2s[i] = A2[i];
    if (tid < 128) redg[tid] = 0.f;
    for (int i = tid; i < 128 * 16; i += 512) red2[i] = 0.f;

    float acc[2][8][4];
    #pragma unroll
    for (int a = 0; a < 2; a++)
        #pragma unroll
        for (int b = 0; b < 8; b++)
            #pragma unroll
            for (int e = 0; e < 4; e++) acc[a][b][e] = 0.f;

    // =================== phase 1: D1 = [h|c] @ W1 ========================
    for (int ch = 0; ch < 6; ch++) {
        int kt = ch * 64;
        __syncthreads();
        // A tile [128 x 64] f32 -> split bf16 hi/lo into R1
        {
            const float* src; int stride, cb;
            if (kt < 256) { src = h; stride = 256; cb = kt; }
            else          { src = c; stride = 128; cb = kt - 256; }
            #pragma unroll
            for (int i = 0; i < 4; i++) {
                int idx = tid + i * 512;
                int row = idx >> 4, c4 = (idx & 15) * 4;
                int gr = r0 + row;
                float4 v = make_float4(0.f, 0.f, 0.f, 0.f);
                if (gr < N) v = *(const float4*)(src + (size_t)gr * stride + cb + c4);
                __nv_bfloat16 h0 = __float2bfloat16(v.x), h1 = __float2bfloat16(v.y);
                __nv_bfloat16 h2 = __float2bfloat16(v.z), h3 = __float2bfloat16(v.w);
                __nv_bfloat16 l0 = __float2bfloat16(v.x - __bfloat162float(h0));
                __nv_bfloat16 l1 = __float2bfloat16(v.y - __bfloat162float(h1));
                __nv_bfloat16 l2 = __float2bfloat16(v.z - __bfloat162float(h2));
                __nv_bfloat16 l3 = __float2bfloat16(v.w - __bfloat162float(h3));
                uint32_t off = SW128((uint32_t)(row * 128 + c4 * 2));
                uint2 ph_ = make_uint2(
                    (uint32_t)__bfloat16_as_ushort(h0) | ((uint32_t)__bfloat16_as_ushort(h1) << 16),
                    (uint32_t)__bfloat16_as_ushort(h2) | ((uint32_t)__bfloat16_as_ushort(h3) << 16));
                uint2 pl_ = make_uint2(
                    (uint32_t)__bfloat16_as_ushort(l0) | ((uint32_t)__bfloat16_as_ushort(l1) << 16),
                    (uint32_t)__bfloat16_as_ushort(l2) | ((uint32_t)__bfloat16_as_ushort(l3) << 16));
                *(uint2*)(smem + R1 + off) = ph_;
                *(uint2*)(smem + R1 + 16384 + off) = pl_;
            }
        }
        // B tile [256 n x 64 k] pre-split bf16 -> R2
        #pragma unroll
        for (int i = 0; i < 4; i++) {
            int u = tid + i * 512;
            int row = u >> 3, c8 = (u & 7) * 8;
            uint4 vh = *(const uint4*)(d_w1t_hi + (size_t)row * 384 + kt + c8);
            uint4 vl = *(const uint4*)(d_w1t_lo + (size_t)row * 384 + kt + c8);
            uint32_t off = SW128((uint32_t)(row * 128 + c8 * 2));
            *(uint4*)(smem + R2 + off) = vh;
            *(uint4*)(smem + R2 + 32768 + off) = vl;
        }
        __syncthreads();
        #pragma unroll
        for (int ks = 0; ks < 4; ks++) {
            int kb = ks * 32;
            uint32_t ah[2][4], al[2][4];
            #pragma unroll
            for (int mt = 0; mt < 2; mt++) {
                int mb = wm * 32 + mt * 16 + (lane & 7) + ((lane & 8) ? 8 : 0);
                uint32_t ao = SW128((uint32_t)(mb * 128 + kb + ((lane & 16) ? 16 : 0)));
                LDSM_X4(ah[mt], sb + R1 + ao);
                LDSM_X4(al[mt], sb + R1 + 16384 + ao);
            }
            #pragma unroll
            for (int nt = 0; nt < 8; nt++) {
                int nb = wn * 64 + nt * 8 + (lane & 7);
                uint32_t bo = SW128((uint32_t)(nb * 128 + kb + ((lane & 8) ? 16 : 0)));
                uint32_t bh[2], bl[2];
                LDSM_X2(bh, sb + R2 + bo);
                LDSM_X2(bl, sb + R2 + 32768 + bo);
                #pragma unroll
                for (int mt = 0; mt < 2; mt++) {
                    MMA16816(acc[mt][nt], ah[mt], bh);
                    MMA16816(acc[mt][nt], al[mt], bh);
                    MMA16816(acc[mt][nt], ah[mt], bl);
                }
            }
        }
    }
    // =================== epilogue 1: gate + hg ===========================
    #pragma unroll
    for (int mt = 0; mt < 2; mt++) {
        float s0 = 0.f, s1 = 0.f;
        #pragma unroll
        for (int nt = 0; nt < 8; nt++) {
            int n = wn * 64 + nt * 8 + (lane & 3) * 2;
            float b0v = bias1[n], b1v = bias1[n + 1];
            float w0 = w2s[n], w1v = w2s[n + 1];
            s0 += geluf(acc[mt][nt][0] + b0v) * w0 + geluf(acc[mt][nt][1] + b1v) * w1v;
            s1 += geluf(acc[mt][nt][2] + b0v) * w0 + geluf(acc[mt][nt][3] + b1v) * w1v;
        }
        s0 += __shfl_xor_sync(0xffffffffu, s0, 1);
        s0 += __shfl_xor_sync(0xffffffffu, s0, 2);
        s1 += __shfl_xor_sync(0xffffffffu, s1, 1);
        s1 += __shfl_xor_sync(0xffffffffu, s1, 2);
        if ((lane & 3) == 0) {
            int r = wm * 32 + mt * 16 + (lane >> 2);
            atomicAdd(&redg[r], s0);
            atomicAdd(&redg[r + 8], s1);
        }
    }
    __syncthreads();
    if (tid < 128) alpha[tid] = 1.f / (1.f + expf(-(redg[tid] + b2[0])));
    __syncthreads();
    // hg = alpha * h: write f32 to global (for k_pool) + split into smem
    #pragma unroll
    for (int i = 0; i < 16; i++) {
        int idx = tid + i * 512;                 // 128 rows * 64 float4
        int row = idx >> 6, c4 = (idx & 63) * 4;
        int gr = r0 + row;
        float4 o = make_float4(0.f, 0.f, 0.f, 0.f);
        if (gr < N) {
            float4 hv = *(const float4*)(h + (size_t)gr * 256 + c4);
            float a = alpha[row];
            o = make_float4(a * hv.x, a * hv.y, a * hv.z, a * hv.w);
            *(float4*)(d_hg + (size_t)gr * 256 + c4) = o;
        }
        __nv_bfloat16 h0 = __float2bfloat16(o.x), h1 = __float2bfloat16(o.y);
        __nv_bfloat16 h2 = __float2bfloat16(o.z), h3 = __float2bfloat16(o.w);
        __nv_bfloat16 l0 = __float2bfloat16(o.x - __bfloat162float(h0));
        __nv_bfloat16 l1 = __float2bfloat16(o.y - __bfloat162float(h1));
        __nv_bfloat16 l2 = __float2bfloat16(o.z - __bfloat162float(h2));
        __nv_bfloat16 l3 = __float2bfloat16(o.w - __bfloat162float(h3));
        int chn = c4 >> 6, kloc = c4 & 63;
        uint32_t base = (chn < 3) ? (R3 + chn * 32768) : R1;
        uint32_t off = SW128((uint32_t)(row * 128 + kloc * 2));
        uint2 ph_ = make_uint2(
            (uint32_t)__bfloat16_as_ushort(h0) | ((uint32_t)__bfloat16_as_ushort(h1) << 16),
            (uint32_t)__bfloat16_as_ushort(h2) | ((uint32_t)__bfloat16_as_ushort(h3) << 16));
        uint2 pl_ = make_uint2(
            (uint32_t)__bfloat16_as_ushort(l0) | ((uint32_t)__bfloat16_as_ushort(l1) << 16),
            (uint32_t)__bfloat16_as_ushort(l2) | ((uint32_t)__bfloat16_as_ushort(l3) << 16));
        *(uint2*)(smem + base + off) = ph_;
        *(uint2*)(smem + base + 16384 + off) = pl_;
    }
    // =================== phase 2: D2 = hg @ A1 ===========================
    #pragma unroll
    for (int a = 0; a < 2; a++)
        #pragma unroll
        for (int b = 0; b < 8; b++)
            #pragma unroll
            for (int e = 0; e < 4; e++) acc[a][b][e] = 0.f;

    for (int ch = 0; ch < 4; ch++) {
        int kt = ch * 64;
        __syncthreads();
        #pragma unroll
        for (int i = 0; i < 4; i++) {
            int u = tid + i * 512;
            int row = u >> 3, c8 = (u & 7) * 8;
            uint4 vh = *(const uint4*)(d_a1t_hi + (size_t)row * 256 + kt + c8);
            uint4 vl = *(const uint4*)(d_a1t_lo + (size_t)row * 256 + kt + c8);
            uint32_t off = SW128((uint32_t)(row * 128 + c8 * 2));
            *(uint4*)(smem + R2 + off) = vh;
            *(uint4*)(smem + R2 + 32768 + off) = vl;
        }
        __syncthreads();
        uint32_t abase = sb + ((ch < 3) ? (R3 + ch * 32768) : R1);
        #pragma unroll
        for (int ks = 0; ks < 4; ks++) {
            int kb = ks * 32;
            uint32_t ah[2][4], al[2][4];
            #pragma unroll
            for (int mt = 0; mt < 2; mt++) {
                int mb = wm * 32 + mt * 16 + (lane & 7) + ((lane & 8) ? 8 : 0);
                uint32_t ao = SW128((uint32_t)(mb * 128 + kb + ((lane & 16) ? 16 : 0)));
                LDSM_X4(ah[mt], abase + ao);
                LDSM_X4(al[mt], abase + 16384 + ao);
            }
            #pragma unroll
            for (int nt = 0; nt < 8; nt++) {
                int nb = wn * 64 + nt * 8 + (lane & 7);
                uint32_t bo = SW128((uint32_t)(nb * 128 + kb + ((lane & 8) ? 16 : 0)));
                uint32_t bh[2], bl[2];
                LDSM_X2(bh, sb + R2 + bo);
                LDSM_X2(bl, sb + R2 + 32768 + bo);
                #pragma unroll
                for (int mt = 0; mt < 2; mt++) {
                    MMA16816(acc[mt][nt], ah[mt], bh);
                    MMA16816(acc[mt][nt], al[mt], bh);
                    MMA16816(acc[mt][nt], ah[mt], bl);
                }
            }
        }
    }
    // =================== epilogue 2: @A2 + softmax -> d_S ================
    #pragma unroll
    for (int mt = 0; mt < 2; mt++) {
        float l0[16], l1[16];
        #pragma unroll
        for (int k = 0; k < 16; k++) { l0[k] = 0.f; l1[k] = 0.f; }
        #pragma unroll
        for (int nt = 0; nt < 8; nt++) {
            int n = wn * 64 + nt * 8 + (lane & 3) * 2;
            #pragma unroll
            for (int e = 0; e < 4; e++) {
                int col = n + (e & 1);
                float v = geluf(acc[mt][nt][e] + ab1s[col]);
                const float* ar = &a2s[col * 16];
                float* dst = (e < 2) ? l0 : l1;
                #pragma unroll
                for (int k = 0; k < 16; k++) dst[k] += v * ar[k];
            }
        }
        #pragma unroll
        for (int k = 0; k < 16; k++) {
            l0[k] += __shfl_xor_sync(0xffffffffu, l0[k], 1);
            l0[k] += __shfl_xor_sync(0xffffffffu, l0[k], 2);
            l1[k] += __shfl_xor_sync(0xffffffffu, l1[k], 1);
            l1[k] += __shfl_xor_sync(0xffffffffu, l1[k], 2);
        }
        if ((lane & 3) == 0) {
            int r = wm * 32 + mt * 16 + (lane >> 2);
            #pragma unroll
            for (int k = 0; k < 16; k++) {
                atomicAdd(&red2[r * 16 + k], l0[k]);
                atomicAdd(&red2[(r + 8) * 16 + k], l1[k]);
            }
        }
    }
    __syncthreads();
    if (tid < 128) {
        int gr = r0 + tid;
        if (gr < N) {
            float l[16], mx = -1e30f;
            #pragma unroll
            for (int k = 0; k < 16; k++) {
                l[k] = red2[tid * 16 + k] + ab2s[k];
                mx = fmaxf(mx, l[k]);
            }
            float s = 0.f;
            #pragma unroll
            for (int k = 0; k < 16; k++) { l[k] = expf(l[k] - mx); s += l[k]; }
            float inv = 1.f / s;
            #pragma unroll
            for (int k4 = 0; k4 < 4; k4++) {
                float4 o = make_float4(l[4*k4] * inv, l[4*k4+1] * inv,
                                       l[4*k4+2] * inv, l[4*k4+3] * inv);
                *(float4*)(d_S + (size_t)gr * 16 + 4 * k4) = o;
            }
        }
    }
}

// ---------------- K3: segment pool ---------------------------------------
__global__ __launch_bounds__(256) void k_pool(void) {
    int b = blockIdx.x, tid = threadIdx.x;
    int s = d_seg[b], e = d_seg[b + 1];
    float acc[16];
    #pragma unroll
    for (int k = 0; k < 16; k++) acc[k] = 0.f;
    __shared__ __align__(16) float ssh[16 * 16];
    for (int n0 = s; n0 < e; n0 += 16) {
        int cnt = min(16, e - n0);
        if (tid < cnt * 16) ssh[tid] = d_S[(size_t)n0 * KCL + tid];
        __syncthreads();
        for (int a = 0; a < cnt; a++) {
            float hgv = d_hg[(size_t)(n0 + a) * HID + tid];
            const float4* sp = (const float4*)&ssh[a * 16];
            float4 s0 = sp[0], s1 = sp[1], s2 = sp[2], s3 = sp[3];
            acc[0]  += s0.x * hgv; acc[1]  += s0.y * hgv;
            acc[2]  += s0.z * hgv; acc[3]  += s0.w * hgv;
            acc[4]  += s1.x * hgv; acc[5]  += s1.y * hgv;
            acc[6]  += s1.z * hgv; acc[7]  += s1.w * hgv;
            acc[8]  += s2.x * hgv; acc[9]  += s2.y * hgv;
            acc[10] += s2.z * hgv; acc[11] += s2.w * hgv;
            acc[12] += s3.x * hgv; acc[13] += s3.y * hgv;
            acc[14] += s3.z * hgv; acc[15] += s3.w * hgv;
        }
        __syncthreads();
    }
    #pragma unroll
    for (int k = 0; k < 16; k++)
        d_cluster[((size_t)b * 16 + k) * HID + tid] = acc[k];
}

// ---------------- K5: attention readout + folded proj + LN ---------------
__global__ __launch_bounds__(256) void k_readout(
    const float* __restrict__ gamma, const float* __restrict__ beta,
    float* __restrict__ out) {
    int b = blockIdx.x, tid = threadIdx.x, lane = tid & 31, p = tid >> 5;
    __shared__ float cl[16][HID];
    __shared__ float qm[HID][9];
    __shared__ float msh[PH][HID];
    __shared__ float wsh[PH][16];
    __shared__ float red[HID];
    __shared__ float bqs[PH];
    #pragma unroll
    for (int k = 0; k < 16; k++)
        cl[k][tid] = d_cluster[((size_t)b * 16 + k) * HID + tid];
    for (int idx = tid; idx < HID * PH; idx += 256)
        qm[idx >> 3][idx & 7] = d_Qm[idx];
    if (tid < PH) bqs[tid] = d_bq[tid];
    __syncthreads();

    float ml = 0.f;
    for (int k = 0; k < 16; k++) {
        float part = 0.f;
        #pragma unroll
        for (int i = 0; i < 8; i++) { int jj = lane + 32 * i; part += cl[k][jj] * qm[jj][p]; }
        #pragma unroll
        for (int off = 16; off; off >>= 1)
            part += __shfl_xor_sync(0xffffffffu, part, off);
        if (lane == k) ml = part;
    }
    const float scale = 0.17677669529663687f;
    if (lane < 16) {
        float lgv = (ml + bqs[p]) * scale;
        float mx = lgv;
        #pragma unroll
        for (int off = 8; off; off >>= 1)
            mx = fmaxf(mx, __shfl_xor_sync(0xffffu, mx, off, 16));
        float e = expf(lgv - mx), su = e;
        #pragma unroll
        for (int off = 8; off; off >>= 1)
            su += __shfl_xor_sync(0xffffu, su, off, 16);
        wsh[p][lane] = e / su;
    }
    __syncthreads();

    #pragma unroll
    for (int pp = 0; pp < PH; pp++) {
        float a = 0.f;
        #pragma unroll
        for (int k = 0; k < 16; k++) a += wsh[pp][k] * cl[k][tid];
        msh[pp][tid] = a;
    }
    __syncthreads();

    float o = d_bv[tid];
    #pragma unroll 8
    for (int i = 0; i < HID; i++)
        o += msh[p][i] * d_Wcv[(size_t)i * HID + tid];

    red[tid] = o; __syncthreads();
    for (int s = 128; s; s >>= 1) { if (tid < s) red[tid] += red[tid + s]; __syncthreads(); }
    float mu = red[0] * (1.f / HID);
    __syncthreads();
    float dv = o - mu;
    red[tid] = dv * dv; __syncthreads();
    for (int s = 128; s; s >>= 1) { if (tid < s) red[tid] += red[tid + s]; __syncthreads(); }
    float var = red[0] * (1.f / HID);
    out[(size_t)b * HID + tid] = dv * rsqrtf(var + 1e-5f) * gamma[tid] + beta[tid];
}

// ---------------- launch --------------------------------------------------
extern "C" void kernel_launch(void* const* d_in, const int* in_sizes, int n_in,
                              void* d_out, int out_size) {
    const float* h_atom = (const float*)d_in[0];
    const float* c_atom = (const float*)d_in[1];
    const int*   batch  = (const int*)  d_in[2];
    const float* W1 = (const float*)d_in[3];
    const float* b1 = (const float*)d_in[4];
    const float* W2 = (const float*)d_in[5];
    const float* b2 = (const float*)d_in[6];
    const float* A1 = (const float*)d_in[7];
    const float* ab1 = (const float*)d_in[8];
    const float* A2 = (const float*)d_in[9];
    const float* ab2 = (const float*)d_in[10];
    const float* Wc = (const float*)d_in[11];
    const float* bc = (const float*)d_in[12];
    const float* q  = (const float*)d_in[13];
    const float* Wk = (const float*)d_in[14];
    const float* Wv = (const float*)d_in[15];
    const float* gamma = (const float*)d_in[16];
    const float* beta  = (const float*)d_in[17];
    float* out = (float*)d_out;

    int N = in_sizes[0] / HID; if (N > NMAX) N = NMAX;
    int B = out_size / HID;    if (B > BMAX) B = BMAX;

    cudaFuncSetAttribute(k_fused, cudaFuncAttributeMaxDynamicSharedMemorySize, SMEMSZ);

    k_seg<<<(N + 255) / 256, 256>>>(batch, N, B);
    k_splitw1<<<384, 256>>>(W1);
    k_splita1<<<256, 256>>>(A1);
    k_u2<<<256, 256>>>(Wk, q);
    k_wcv<<<HID + 1, 256>>>(Wc, Wv, bc);
    k_qm<<<HID + 1, 256>>>(Wc, bc);

    int gtiles = (N + 127) / 128;
    k_fused<<<gtiles, 512, SMEMSZ>>>(h_atom, c_atom, b1, W2, b2, ab1, A2, ab2, N);
    k_pool<<<B, 256>>>();
    k_readout<<<B, 256>>>(gamma, beta, out);
}